// round 4
// baseline (speedup 1.0000x reference)
#include <cuda_runtime.h>
#include <math.h>

#define Nn   60000
#define Dd   512
#define Hh   245
#define NB1  7500   // k1 blocks (8 rows each)
#define NB3  490    // k3b blocks (row halves)
#define RSQD 0.04419417382415922f  // 1/sqrt(512)

// ---------------- scratch (device globals; no runtime allocation) ----------------
__device__ __align__(16) float g_pval[NB1];
__device__               int   g_pidx[NB1];
__device__               int   g_idx;
__device__ __align__(16) float g_Qvec[Dd];
__device__ __align__(16) float g_q[Dd];
__device__ __align__(16) float g_u[8 * Dd];
__device__ __align__(16) float g_c[8];
__device__ __align__(16) float g_scls[8];
__device__ __align__(16) float g_pm[NB3 * 8];
__device__ __align__(16) float g_pl[NB3 * 8];
__device__ __align__(16) float g_pacc[NB3 * 8 * Dd];
__device__ __align__(16) float g_s[8 * Dd];

// ---------------- K1: a1 = sigmoid(inputs @ w_enc + b_enc), argmax partials ------
__global__ void k1_kernel(const float* __restrict__ inp, const float* __restrict__ wenc,
                          const float* __restrict__ benc, float* __restrict__ A1)
{
    int warp = threadIdx.x >> 5, lane = threadIdx.x & 31;
    int row  = blockIdx.x * 8 + warp;   // 7500*8 = 60000 exactly
    const float4* ip = reinterpret_cast<const float4*>(inp + (size_t)row * Dd);
    const float4* wp = reinterpret_cast<const float4*>(wenc);
    float acc = 0.f;
#pragma unroll
    for (int it = 0; it < 4; it++) {
        int i = lane + it * 32;
        float4 a = __ldg(ip + i);
        float4 w = __ldg(wp + i);
        acc += a.x * w.x + a.y * w.y + a.z * w.z + a.w * w.w;
    }
#pragma unroll
    for (int o = 16; o; o >>= 1) acc += __shfl_xor_sync(0xffffffffu, acc, o);
    __shared__ float sv[8];
    __shared__ int   si[8];
    if (lane == 0) {
        float y = acc + benc[0];
        A1[row] = 1.f / (1.f + __expf(-y));   // sigmoid; monotone so argmax(y)=argmax(a1)
        sv[warp] = y; si[warp] = row;
    }
    __syncthreads();
    if (threadIdx.x == 0) {
        float bv = sv[0]; int bi = si[0];
        for (int w = 1; w < 8; w++) { if (sv[w] > bv) { bv = sv[w]; bi = si[w]; } }
        g_pval[blockIdx.x] = bv; g_pidx[blockIdx.x] = bi;
    }
}

// ---------------- K2: argmax reduce + q, u, c, cls score (1 block, 512 thr) ------
__global__ void k2_kernel(const float* __restrict__ inp,
                          const float* __restrict__ wq, const float* __restrict__ bq,
                          const float* __restrict__ wk, const float* __restrict__ bk,
                          const float* __restrict__ cls)
{
    __shared__ float bv[512]; __shared__ int bi[512];
    __shared__ float sQ[512], sq[512], red[512], c8[8];
    int t = threadIdx.x;

    float best = -1e30f; int besti = 0x7fffffff;
    for (int b = t; b < NB1; b += 512) {
        float v = g_pval[b]; int ii = g_pidx[b];
        if (v > best || (v == best && ii < besti)) { best = v; besti = ii; }
    }
    bv[t] = best; bi[t] = besti;
    __syncthreads();
    for (int s = 256; s > 0; s >>= 1) {
        if (t < s) {
            if (bv[t + s] > bv[t] || (bv[t + s] == bv[t] && bi[t + s] < bi[t])) {
                bv[t] = bv[t + s]; bi[t] = bi[t + s];
            }
        }
        __syncthreads();
    }
    int idx = bi[0];
    if (t == 0) g_idx = idx;

    float Qv = inp[(size_t)idx * Dd + t];
    sQ[t] = Qv; g_Qvec[t] = Qv;
    __syncthreads();

    // q = Q @ w_q + b_q
    float a = bq[t];
    for (int d = 0; d < Dd; d++) a += sQ[d] * wq[d * Dd + t];
    sq[t] = a; g_q[t] = a;
    __syncthreads();

    // u[h][d] = sum_{j in head h} w_k[d][j] * q[j], scaled by 1/sqrt(D)
    float ua[8];
#pragma unroll
    for (int h = 0; h < 8; h++) ua[h] = 0.f;
    for (int j = 0; j < Dd; j++) ua[j >> 6] += wk[t * Dd + j] * sq[j];
#pragma unroll
    for (int h = 0; h < 8; h++) { ua[h] *= RSQD; g_u[h * Dd + t] = ua[h]; }

    // c[h] = (b_k . q)_head / sqrt(D)
    red[t] = bk[t] * sq[t];
    __syncthreads();
    if (t < 8) {
        float s = 0.f;
        for (int j = 0; j < 64; j++) s += red[t * 64 + j];
        s *= RSQD; c8[t] = s; g_c[t] = s;
    }
    __syncthreads();

    // cls token raw score per head
    for (int h = 0; h < 8; h++) {
        red[t] = cls[t] * ua[h];
        __syncthreads();
        for (int s = 256; s > 0; s >>= 1) { if (t < s) red[t] += red[t + s]; __syncthreads(); }
        if (t == 0) g_scls[h] = red[0] + c8[h];
        __syncthreads();
    }
}

// ---------------- K3a: i_shift = relu(inputs - Q) --------------------------------
__global__ void k3a_kernel(const float* __restrict__ inp, float* __restrict__ ish)
{
    int gid = blockIdx.x * blockDim.x + threadIdx.x;  // quad index; 30000*256 = 7,680,000 exactly
    int cq = gid & 127;
    float4 v  = reinterpret_cast<const float4*>(inp)[gid];
    float4 qv = reinterpret_cast<const float4*>(g_Qvec)[cq];
    float2 o0 = make_float2(fmaxf(v.x - qv.x, 0.f), fmaxf(v.y - qv.y, 0.f));
    float2 o1 = make_float2(fmaxf(v.z - qv.z, 0.f), fmaxf(v.w - qv.w, 0.f));
    float2* op = reinterpret_cast<float2*>(ish + (size_t)gid * 4);  // 8B aligned (out+2 floats)
    op[0] = o0; op[1] = o1;
}

// ---------------- K3b: conv stencil + scores + online-softmax flash partials -----
__global__ void __launch_bounds__(128)
k3b_kernel(const float* __restrict__ xs,
           const float* __restrict__ convw, const float* __restrict__ convb)
{
    int b    = blockIdx.x;
    int i    = b >> 1;
    int half = b & 1;
    int j0   = half ? 123 : 0;
    int j1   = half ? 245 : 123;
    int c    = threadIdx.x;   // channel quad 0..127
    int d0   = c * 4;

    float4 u4[8];
#pragma unroll
    for (int h = 0; h < 8; h++) u4[h] = *reinterpret_cast<const float4*>(&g_u[h * Dd + d0]);
    float wx[9], wy[9], wz[9], ww[9];
#pragma unroll
    for (int k = 0; k < 9; k++) {
        wx[k] = convw[(d0 + 0) * 9 + k];
        wy[k] = convw[(d0 + 1) * 9 + k];
        wz[k] = convw[(d0 + 2) * 9 + k];
        ww[k] = convw[(d0 + 3) * 9 + k];
    }
    float4 cb = *reinterpret_cast<const float4*>(&convb[d0]);
    float4 acc[8];
#pragma unroll
    for (int h = 0; h < 8; h++) acc[h] = make_float4(0.f, 0.f, 0.f, 0.f);

    __shared__ float sp[4][8];
    __shared__ float shm[8], shl[8], shr[8], shw[8], shc[8];
    if (c < 8) { shm[c] = -1e30f; shl[c] = 0.f; shc[c] = g_c[c]; }
    __syncthreads();
    int warp = c >> 5, lane = c & 31;

    for (int j = j0; j < j1; j++) {
        float4 xx  = cb;
        float4 ctr = make_float4(0.f, 0.f, 0.f, 0.f);
#pragma unroll
        for (int ky = 0; ky < 3; ky++) {
            int gy = i + ky - 1;
            bool ry = (unsigned)gy < (unsigned)Hh;
#pragma unroll
            for (int kx = 0; kx < 3; kx++) {
                int gx = j + kx - 1;
                float4 n = make_float4(0.f, 0.f, 0.f, 0.f);
                if (ry && (unsigned)gx < (unsigned)Hh) {
                    int pp = gy * Hh + gx;
                    int rr = (pp >= Nn) ? (pp - Nn) : pp;   // padded tokens wrap to rows 0..24
                    const float2* p2 = reinterpret_cast<const float2*>(xs + (size_t)rr * Dd + d0);
                    float2 aa = __ldg(p2); float2 bb = __ldg(p2 + 1);
                    n.x = aa.x; n.y = aa.y; n.z = bb.x; n.w = bb.y;
                }
                int k = ky * 3 + kx;
                xx.x += wx[k] * n.x; xx.y += wy[k] * n.y;
                xx.z += wz[k] * n.z; xx.w += ww[k] * n.w;
                if (k == 4) ctr = n;
            }
        }
        // residual: cnn = conv + cnn
        xx.x += ctr.x; xx.y += ctr.y; xx.z += ctr.z; xx.w += ctr.w;

        // score partials (u already scaled by 1/sqrt(D))
        float p[8];
#pragma unroll
        for (int h = 0; h < 8; h++)
            p[h] = xx.x * u4[h].x + xx.y * u4[h].y + xx.z * u4[h].z + xx.w * u4[h].w;
#pragma unroll
        for (int o = 16; o; o >>= 1) {
#pragma unroll
            for (int h = 0; h < 8; h++) p[h] += __shfl_xor_sync(0xffffffffu, p[h], o);
        }
        if (lane < 8) sp[warp][lane] = p[lane];
        __syncthreads();
        if (c < 8) {
            float s  = sp[0][c] + sp[1][c] + sp[2][c] + sp[3][c] + shc[c];
            float mo = shm[c];
            float mn = fmaxf(mo, s);
            float r  = __expf(mo - mn);
            float wv = __expf(s - mn);
            shl[c] = shl[c] * r + wv;
            shm[c] = mn; shr[c] = r; shw[c] = wv;
        }
        __syncthreads();
#pragma unroll
        for (int h = 0; h < 8; h++) {
            float r = shr[h], wv = shw[h];
            acc[h].x = acc[h].x * r + wv * xx.x;
            acc[h].y = acc[h].y * r + wv * xx.y;
            acc[h].z = acc[h].z * r + wv * xx.z;
            acc[h].w = acc[h].w * r + wv * xx.w;
        }
        // next iteration's shr/shw writes are fenced by the sp __syncthreads()
    }

    if (c < 8) { g_pm[b * 8 + c] = shm[c]; g_pl[b * 8 + c] = shl[c]; }
#pragma unroll
    for (int h = 0; h < 8; h++)
        *reinterpret_cast<float4*>(&g_pacc[(size_t)(b * 8 + h) * Dd + d0]) = acc[h];
}

// ---------------- K4: combine flash partials + cls token -> s_h ------------------
__global__ void k4_kernel(const float* __restrict__ cls)
{
    int h = blockIdx.x, t = threadIdx.x;
    __shared__ float red[512];
    __shared__ float ee[512];
    __shared__ float sM, sL;

    float mv = (t < NB3) ? g_pm[t * 8 + h] : -1e30f;
    red[t] = mv;
    __syncthreads();
    for (int s = 256; s > 0; s >>= 1) { if (t < s) red[t] = fmaxf(red[t], red[t + s]); __syncthreads(); }
    if (t == 0) sM = fmaxf(red[0], g_scls[h]);
    __syncthreads();
    float M = sM;

    float e = (t < NB3) ? __expf(g_pm[t * 8 + h] - M) : 0.f;
    ee[t] = e;
    red[t] = (t < NB3) ? g_pl[t * 8 + h] * e : 0.f;
    __syncthreads();
    for (int s = 256; s > 0; s >>= 1) { if (t < s) red[t] += red[t + s]; __syncthreads(); }
    float ecls = __expf(g_scls[h] - M);
    if (t == 0) sL = red[0] + ecls;
    __syncthreads();
    float L = sL;

    float acc = 0.f;
    for (int b = 0; b < NB3; b++) acc += ee[b] * g_pacc[(size_t)(b * 8 + h) * Dd + t];
    acc += ecls * cls[t];
    g_s[h * Dd + t] = acc / L;
}

// ---------------- K5: epilogue (attention output -> MLP -> classifier) -----------
__global__ void k5_kernel(const float* __restrict__ wv, const float* __restrict__ bv,
                          const float* __restrict__ wo, const float* __restrict__ bo,
                          const float* __restrict__ wfc, const float* __restrict__ bfc,
                          float* __restrict__ outv)
{
    __shared__ float sO[512], r0[512], r1[512];
    int j = threadIdx.x, h = j >> 6;

    float a = 0.f;
    for (int d = 0; d < Dd; d++) a += g_s[h * Dd + d] * wv[d * Dd + j];
    float O = g_q[j] + a + bv[j];
    sO[j] = O;
    __syncthreads();

    float t2 = bo[j];
    for (int d = 0; d < Dd; d++) t2 += sO[d] * wo[d * Dd + j];
    float O2 = O + fmaxf(t2, 0.f);

    r0[j] = O2 * wfc[j * 2 + 0];
    r1[j] = O2 * wfc[j * 2 + 1];
    __syncthreads();
    for (int s = 256; s > 0; s >>= 1) {
        if (j < s) { r0[j] += r0[j + s]; r1[j] += r1[j + s]; }
        __syncthreads();
    }
    if (j == 0) { outv[0] = r0[0] + bfc[0]; outv[1] = r1[0] + bfc[1]; }
}

// ---------------- launch ----------------------------------------------------------
extern "C" void kernel_launch(void* const* d_in, const int* in_sizes, int n_in,
                              void* d_out, int out_size)
{
    (void)in_sizes; (void)n_in; (void)out_size;
    const float* inp   = (const float*)d_in[0];
    const float* wenc  = (const float*)d_in[1];
    const float* benc  = (const float*)d_in[2];
    const float* cls   = (const float*)d_in[3];
    const float* convw = (const float*)d_in[4];
    const float* convb = (const float*)d_in[5];
    const float* wq    = (const float*)d_in[6];
    const float* bq    = (const float*)d_in[7];
    const float* wk    = (const float*)d_in[8];
    const float* bk    = (const float*)d_in[9];
    const float* wv    = (const float*)d_in[10];
    const float* bvv   = (const float*)d_in[11];
    const float* wo    = (const float*)d_in[12];
    const float* bo    = (const float*)d_in[13];
    const float* wfc   = (const float*)d_in[14];
    const float* bfc   = (const float*)d_in[15];

    float* out    = (float*)d_out;
    float* ishift = out + 2;                          // i_shift: (1, 60000, 512)
    float* A1     = out + 2 + (size_t)Nn * Dd;        // A1: (1, 60000)

    k1_kernel <<<NB1, 256>>>(inp, wenc, benc, A1);
    k2_kernel <<<1, 512>>>(inp, wq, bq, wk, bk, cls);
    k3a_kernel<<<30000, 256>>>(inp, ishift);
    k3b_kernel<<<NB3, 128>>>(ishift, convw, convb);
    k4_kernel <<<8, 512>>>(cls);
    k5_kernel <<<1, 512>>>(wv, bvv, wo, bo, wfc, bfc, out);
}

// round 6
// speedup vs baseline: 1.1874x; 1.1874x over previous
#include <cuda_runtime.h>
#include <math.h>

#define Nn   60000
#define Dd   512
#define Hh   245
#define NB1  7500   // k1 blocks (8 rows each)
#define NB3  490    // k3 blocks (row halves)
#define CCH  16     // softmax chunk (tokens per sync pair)
#define RSQD 0.04419417382415922f  // 1/sqrt(512)

// ---------------- scratch (device globals; no runtime allocation) ----------------
__device__ __align__(16) float g_pval[NB1];
__device__               int   g_pidx[NB1];
__device__               int   g_idx;
__device__ __align__(16) float g_Qvec[Dd];
__device__ __align__(16) float g_q[Dd];
__device__ __align__(16) float g_u[8 * Dd];
__device__ __align__(16) float g_c[8];
__device__ __align__(16) float g_scls[8];
__device__ __align__(16) float g_pm[NB3 * 8];
__device__ __align__(16) float g_pl[NB3 * 8];
__device__ __align__(16) float g_pacc[NB3 * 8 * Dd];
__device__ __align__(16) float g_s[8 * Dd];
__device__ __align__(16) float g_ee[8 * 512];
__device__ __align__(16) float g_M8[8];
__device__ __align__(16) float g_L8[8];
__device__ __align__(16) float g_s4[32 * Dd];
__device__ __align__(16) float g_O[Dd];
__device__ __align__(16) float g_O2[Dd];

// ---------------- K1: a1 = sigmoid(inputs @ w_enc + b_enc), argmax partials ------
__global__ void k1_kernel(const float* __restrict__ inp, const float* __restrict__ wenc,
                          const float* __restrict__ benc, float* __restrict__ A1)
{
    int warp = threadIdx.x >> 5, lane = threadIdx.x & 31;
    int row  = blockIdx.x * 8 + warp;   // 7500*8 = 60000 exactly
    const float4* ip = reinterpret_cast<const float4*>(inp + (size_t)row * Dd);
    const float4* wp = reinterpret_cast<const float4*>(wenc);
    float acc = 0.f;
#pragma unroll
    for (int it = 0; it < 4; it++) {
        int i = lane + it * 32;
        float4 a = __ldg(ip + i);
        float4 w = __ldg(wp + i);
        acc += a.x * w.x + a.y * w.y + a.z * w.z + a.w * w.w;
    }
#pragma unroll
    for (int o = 16; o; o >>= 1) acc += __shfl_xor_sync(0xffffffffu, acc, o);
    __shared__ float sv[8];
    __shared__ int   si[8];
    if (lane == 0) {
        float y = acc + benc[0];
        A1[row] = 1.f / (1.f + __expf(-y));   // sigmoid; monotone so argmax(y)=argmax(a1)
        sv[warp] = y; si[warp] = row;
    }
    __syncthreads();
    if (threadIdx.x == 0) {
        float bv = sv[0]; int bi = si[0];
        for (int w = 1; w < 8; w++) { if (sv[w] > bv) { bv = sv[w]; bi = si[w]; } }
        g_pval[blockIdx.x] = bv; g_pidx[blockIdx.x] = bi;
    }
}

// ---------------- K2a: argmax reduce + Q vector (1 block) ------------------------
__global__ void k2a_kernel(const float* __restrict__ inp)
{
    __shared__ float bv[512]; __shared__ int bi[512];
    int t = threadIdx.x;
    float best = -1e30f; int besti = 0x7fffffff;
    for (int b = t; b < NB1; b += 512) {
        float v = g_pval[b]; int ii = g_pidx[b];
        if (v > best || (v == best && ii < besti)) { best = v; besti = ii; }
    }
    bv[t] = best; bi[t] = besti;
    __syncthreads();
    for (int s = 256; s > 0; s >>= 1) {
        if (t < s) {
            if (bv[t + s] > bv[t] || (bv[t + s] == bv[t] && bi[t + s] < bi[t])) {
                bv[t] = bv[t + s]; bi[t] = bi[t + s];
            }
        }
        __syncthreads();
    }
    int idx = bi[0];
    if (t == 0) g_idx = idx;
    g_Qvec[t] = inp[(size_t)idx * Dd + t];
}

// ---------------- K2b: q = Q @ w_q + b_q (16 blocks x 32) ------------------------
__global__ void k2b_kernel(const float* __restrict__ wq, const float* __restrict__ bq)
{
    __shared__ float sQ[512];
    int tid = threadIdx.x;
    int j = blockIdx.x * 32 + tid;
#pragma unroll
    for (int k = 0; k < 16; k++) sQ[tid + k * 32] = g_Qvec[tid + k * 32];
    __syncthreads();
    float a = bq[j];
#pragma unroll 8
    for (int d = 0; d < Dd; d++) a += sQ[d] * __ldg(&wq[d * Dd + j]);
    g_q[j] = a;
}

// ---------------- K2c: u[h][t] = (w_k row t . q)_head / sqrt(D) (8 blocks x 64) --
__global__ void k2c_kernel(const float* __restrict__ wk)
{
    __shared__ float sq[512];
    int tid = threadIdx.x;
    int t = blockIdx.x * 64 + tid;
#pragma unroll
    for (int k = 0; k < 8; k++) sq[tid + k * 64] = g_q[tid + k * 64];
    __syncthreads();
    const float4* wrow = reinterpret_cast<const float4*>(wk + (size_t)t * Dd);
#pragma unroll
    for (int h = 0; h < 8; h++) {
        float a = 0.f;
#pragma unroll 4
        for (int jj = 0; jj < 16; jj++) {
            float4 w = __ldg(wrow + h * 16 + jj);
            int j = (h * 16 + jj) * 4;
            a += w.x * sq[j] + w.y * sq[j + 1] + w.z * sq[j + 2] + w.w * sq[j + 3];
        }
        g_u[h * Dd + t] = a * RSQD;
    }
}

// ---------------- K2d: c[h] and cls raw score (1 block) --------------------------
__global__ void k2d_kernel(const float* __restrict__ bk, const float* __restrict__ cls)
{
    __shared__ float red[512]; __shared__ float c8[8];
    int t = threadIdx.x;
    red[t] = bk[t] * g_q[t];
    __syncthreads();
    if (t < 8) {
        float s = 0.f;
        for (int j = 0; j < 64; j++) s += red[t * 64 + j];
        s *= RSQD; c8[t] = s; g_c[t] = s;
    }
    __syncthreads();
    for (int h = 0; h < 8; h++) {
        red[t] = cls[t] * g_u[h * Dd + t];
        __syncthreads();
        for (int s = 256; s > 0; s >>= 1) { if (t < s) red[t] += red[t + s]; __syncthreads(); }
        if (t == 0) g_scls[h] = red[0] + c8[h];
        __syncthreads();
    }
}

// ---------------- K3: fused relu-shift + conv stencil + flash softmax ------------
__device__ __forceinline__ float2 loadxs(const float* __restrict__ inp,
                                         int gy, int gx, int d0, float2 qv)
{
    if ((unsigned)gy >= (unsigned)Hh || (unsigned)gx >= (unsigned)Hh)
        return make_float2(0.f, 0.f);
    int pp = gy * Hh + gx;
    if (pp >= Nn) pp -= Nn;   // padded tokens wrap to tokens 0..24
    float2 v = __ldg(reinterpret_cast<const float2*>(inp + (size_t)pp * Dd + d0));
    return make_float2(fmaxf(v.x - qv.x, 0.f), fmaxf(v.y - qv.y, 0.f));
}

__global__ void __launch_bounds__(256)
k3_kernel(const float* __restrict__ inp, float* __restrict__ ish,
          const float* __restrict__ convw, const float* __restrict__ convb)
{
    int b    = blockIdx.x;
    int i    = b >> 1;
    int half = b & 1;
    int j0   = half ? 123 : 0;
    int j1   = half ? 245 : 123;
    int c    = threadIdx.x;          // channel pair 0..255
    int d0   = c * 2;
    int warp = c >> 5, lane = c & 31;

    __shared__ float sxx[CCH * Dd];        // 32 KB conv-output stash
    __shared__ float sp[CCH][8][8];        // [token][warp][head] partial dots
    __shared__ float swf[CCH][8];          // softmax weights
    __shared__ float sR[8];                // rescale factor per head
    __shared__ float shm[8], shl[8], shc[8];

    float2 qv = *reinterpret_cast<const float2*>(g_Qvec + d0);
    float2 uu[8];
#pragma unroll
    for (int h = 0; h < 8; h++) uu[h] = *reinterpret_cast<const float2*>(g_u + h * Dd + d0);
    float w0[9], w1[9];
#pragma unroll
    for (int k = 0; k < 9; k++) {
        w0[k] = convw[(d0 + 0) * 9 + k];
        w1[k] = convw[(d0 + 1) * 9 + k];
    }
    float2 cb2 = *reinterpret_cast<const float2*>(convb + d0);
    float2 acc[8];
#pragma unroll
    for (int h = 0; h < 8; h++) acc[h] = make_float2(0.f, 0.f);

    if (c < 8) { shm[c] = -1e30f; shl[c] = 0.f; shc[c] = g_c[c]; }
    __syncthreads();

    // rolling 3x3 stencil window: rows A=i-1, B=i, C=i+1; cols 0,1,2 = j-1, j, j+1
    float2 wA0, wA1, wA2, wB0, wB1, wB2, wC0, wC1, wC2;
    wA0 = loadxs(inp, i - 1, j0 - 1, d0, qv); wA1 = loadxs(inp, i - 1, j0, d0, qv);
    wB0 = loadxs(inp, i,     j0 - 1, d0, qv); wB1 = loadxs(inp, i,     j0, d0, qv);
    wC0 = loadxs(inp, i + 1, j0 - 1, d0, qv); wC1 = loadxs(inp, i + 1, j0, d0, qv);

    for (int jb = j0; jb < j1; jb += CCH) {
        int cn = min(CCH, j1 - jb);
        // ---- phase A: conv + scores, no block syncs ----
        for (int t = 0; t < cn; t++) {
            int j = jb + t;
            wA2 = loadxs(inp, i - 1, j + 1, d0, qv);
            wB2 = loadxs(inp, i,     j + 1, d0, qv);
            wC2 = loadxs(inp, i + 1, j + 1, d0, qv);

            float2 xx = cb2;
            xx.x += w0[0] * wA0.x + w0[1] * wA1.x + w0[2] * wA2.x
                  + w0[3] * wB0.x + w0[4] * wB1.x + w0[5] * wB2.x
                  + w0[6] * wC0.x + w0[7] * wC1.x + w0[8] * wC2.x;
            xx.y += w1[0] * wA0.y + w1[1] * wA1.y + w1[2] * wA2.y
                  + w1[3] * wB0.y + w1[4] * wB1.y + w1[5] * wB2.y
                  + w1[6] * wC0.y + w1[7] * wC1.y + w1[8] * wC2.y;
            xx.x += wB1.x; xx.y += wB1.y;        // residual: conv + cnn

            int pp = i * Hh + j;
            if (pp < Nn)                          // i_shift output (owned center)
                *reinterpret_cast<float2*>(ish + (size_t)pp * Dd + d0) = wB1;

            *reinterpret_cast<float2*>(&sxx[t * Dd + d0]) = xx;

            float p[8];
#pragma unroll
            for (int h = 0; h < 8; h++) p[h] = xx.x * uu[h].x + xx.y * uu[h].y;
#pragma unroll
            for (int o = 16; o; o >>= 1) {
#pragma unroll
                for (int h = 0; h < 8; h++) p[h] += __shfl_xor_sync(0xffffffffu, p[h], o);
            }
            if (lane < 8) {
                float pv = p[0];
                if (lane == 1) pv = p[1];
                if (lane == 2) pv = p[2];
                if (lane == 3) pv = p[3];
                if (lane == 4) pv = p[4];
                if (lane == 5) pv = p[5];
                if (lane == 6) pv = p[6];
                if (lane == 7) pv = p[7];
                sp[t][warp][lane] = pv;
            }
            wA0 = wA1; wA1 = wA2;
            wB0 = wB1; wB1 = wB2;
            wC0 = wC1; wC1 = wC2;
        }
        __syncthreads();
        // ---- phase B: chunk softmax finalize (8 threads) ----
        if (c < 8) {
            float mold = shm[c], l = shl[c], cc = shc[c];
            float mx = mold;
            for (int t = 0; t < cn; t++) {
                float s = sp[t][0][c] + sp[t][1][c] + sp[t][2][c] + sp[t][3][c]
                        + sp[t][4][c] + sp[t][5][c] + sp[t][6][c] + sp[t][7][c] + cc;
                sp[t][0][c] = s;                 // stash final score
                mx = fmaxf(mx, s);
            }
            float R = __expf(mold - mx);
            float ls = l * R;
            for (int t = 0; t < cn; t++) {
                float w = __expf(sp[t][0][c] - mx);
                swf[t][c] = w; ls += w;
            }
            sR[c] = R; shm[c] = mx; shl[c] = ls;
        }
        __syncthreads();
        // ---- phase C: weighted accumulate ----
#pragma unroll
        for (int h = 0; h < 8; h++) { float R = sR[h]; acc[h].x *= R; acc[h].y *= R; }
        for (int t = 0; t < cn; t++) {
            float2 xx = *reinterpret_cast<float2*>(&sxx[t * Dd + d0]);
#pragma unroll
            for (int h = 0; h < 8; h++) {
                float w = swf[t][h];
                acc[h].x += w * xx.x; acc[h].y += w * xx.y;
            }
        }
        __syncthreads();   // protect sxx/sp before next chunk overwrites
    }

    if (c < 8) { g_pm[b * 8 + c] = shm[c]; g_pl[b * 8 + c] = shl[c]; }
#pragma unroll
    for (int h = 0; h < 8; h++)
        *reinterpret_cast<float2*>(&g_pacc[(size_t)(b * 8 + h) * Dd + d0]) = acc[h];
}

// ---------------- K4a: per-head global M, L and block weights --------------------
__global__ void k4a_kernel()
{
    int h = blockIdx.x, t = threadIdx.x;
    __shared__ float red[512]; __shared__ float sM;
    float mv = (t < NB3) ? g_pm[t * 8 + h] : -1e30f;
    red[t] = mv;
    __syncthreads();
    for (int s = 256; s > 0; s >>= 1) { if (t < s) red[t] = fmaxf(red[t], red[t + s]); __syncthreads(); }
    if (t == 0) sM = fmaxf(red[0], g_scls[h]);
    __syncthreads();
    float M = sM;
    float ee = (t < NB3) ? __expf(g_pm[t * 8 + h] - M) : 0.f;
    g_ee[h * 512 + t] = ee;
    red[t] = (t < NB3) ? g_pl[t * 8 + h] * ee : 0.f;
    __syncthreads();
    for (int s = 256; s > 0; s >>= 1) { if (t < s) red[t] += red[t + s]; __syncthreads(); }
    if (t == 0) { g_M8[h] = M; g_L8[h] = red[0] + __expf(g_scls[h] - M); }
}

// ---------------- K4b: weighted partial accumulate (32 blocks) -------------------
__global__ void k4b_kernel()
{
    int h = blockIdx.x >> 2, part = blockIdx.x & 3;
    int t = threadIdx.x;
    int b0 = part * 123, b1 = min(NB3, b0 + 123);
    float a = 0.f;
#pragma unroll 4
    for (int bb = b0; bb < b1; bb++)
        a += g_ee[h * 512 + bb] * g_pacc[((size_t)bb * 8 + h) * Dd + t];
    g_s4[blockIdx.x * Dd + t] = a;
}

// ---------------- K4c: combine partials + cls token -> s_h -----------------------
__global__ void k4c_kernel(const float* __restrict__ cls)
{
    int h = blockIdx.x, t = threadIdx.x;
    float a = g_s4[(h * 4 + 0) * Dd + t] + g_s4[(h * 4 + 1) * Dd + t]
            + g_s4[(h * 4 + 2) * Dd + t] + g_s4[(h * 4 + 3) * Dd + t];
    a += __expf(g_scls[h] - g_M8[h]) * cls[t];
    g_s[h * Dd + t] = a / g_L8[h];
}

// ---------------- K5a: O = q + s @ w_v + b_v (16 blocks x 32) --------------------
__global__ void k5a_kernel(const float* __restrict__ wv, const float* __restrict__ bv)
{
    __shared__ float ss[512];
    int tid = threadIdx.x;
    int j = blockIdx.x * 32 + tid;
    int h = j >> 6;   // constant per block
#pragma unroll
    for (int k = 0; k < 16; k++) ss[tid + k * 32] = g_s[h * Dd + tid + k * 32];
    __syncthreads();
    float a = 0.f;
#pragma unroll 8
    for (int d = 0; d < Dd; d++) a += ss[d] * __ldg(&wv[d * Dd + j]);
    g_O[j] = g_q[j] + a + bv[j];
}

// ---------------- K5b: O2 = O + relu(O @ w_o + b_o) (16 blocks x 32) -------------
__global__ void k5b_kernel(const float* __restrict__ wo, const float* __restrict__ bo)
{
    __shared__ float sO[512];
    int tid = threadIdx.x;
    int j = blockIdx.x * 32 + tid;
#pragma unroll
    for (int k = 0; k < 16; k++) sO[tid + k * 32] = g_O[tid + k * 32];
    __syncthreads();
    float a = bo[j];
#pragma unroll 8
    for (int d = 0; d < Dd; d++) a += sO[d] * __ldg(&wo[d * Dd + j]);
    g_O2[j] = g_O[j] + fmaxf(a, 0.f);
}

// ---------------- K5c: out = O2 @ w_fc + b_fc (1 block) --------------------------
__global__ void k5c_kernel(const float* __restrict__ wfc, const float* __restrict__ bfc,
                           float* __restrict__ outv)
{
    __shared__ float r0[512], r1[512];
    int j = threadIdx.x;
    float v = g_O2[j];
    r0[j] = v * wfc[j * 2 + 0];
    r1[j] = v * wfc[j * 2 + 1];
    __syncthreads();
    for (int s = 256; s > 0; s >>= 1) {
        if (j < s) { r0[j] += r0[j + s]; r1[j] += r1[j + s]; }
        __syncthreads();
    }
    if (j == 0) { outv[0] = r0[0] + bfc[0]; outv[1] = r1[0] + bfc[1]; }
}

// ---------------- launch ----------------------------------------------------------
extern "C" void kernel_launch(void* const* d_in, const int* in_sizes, int n_in,
                              void* d_out, int out_size)
{
    (void)in_sizes; (void)n_in; (void)out_size;
    const float* inp   = (const float*)d_in[0];
    const float* wenc  = (const float*)d_in[1];
    const float* benc  = (const float*)d_in[2];
    const float* cls   = (const float*)d_in[3];
    const float* convw = (const float*)d_in[4];
    const float* convb = (const float*)d_in[5];
    const float* wq    = (const float*)d_in[6];
    const float* bq    = (const float*)d_in[7];
    const float* wk    = (const float*)d_in[8];
    const float* bk    = (const float*)d_in[9];
    const float* wv    = (const float*)d_in[10];
    const float* bvv   = (const float*)d_in[11];
    const float* wo    = (const float*)d_in[12];
    const float* bo    = (const float*)d_in[13];
    const float* wfc   = (const float*)d_in[14];
    const float* bfc   = (const float*)d_in[15];

    float* out    = (float*)d_out;
    float* ishift = out + 2;                          // i_shift: (1, 60000, 512)
    float* A1     = out + 2 + (size_t)Nn * Dd;        // A1: (1, 60000)

    k1_kernel <<<NB1, 256>>>(inp, wenc, benc, A1);
    k2a_kernel<<<1, 512>>>(inp);
    k2b_kernel<<<16, 32>>>(wq, bq);
    k2c_kernel<<<8, 64>>>(wk);
    k2d_kernel<<<1, 512>>>(bk, cls);
    k3_kernel <<<NB3, 256>>>(inp, ishift, convw, convb);
    k4a_kernel<<<8, 512>>>();
    k4b_kernel<<<32, 512>>>();
    k4c_kernel<<<8, 512>>>(cls);
    k5a_kernel<<<16, 32>>>(wv, bvv);
    k5b_kernel<<<16, 32>>>(wo, bo);
    k5c_kernel<<<1, 512>>>(wfc, bfc, out);
}

// round 8
// speedup vs baseline: 1.7932x; 1.5102x over previous
#include <cuda_runtime.h>
#include <math.h>

#define Nn   60000
#define Dd   512
#define Hh   245
#define NB1  7500   // k1 blocks (8 rows each)
#define NB3  490    // k3 blocks (row halves)
#define CCH  16     // softmax chunk (tokens per sync group)
#define RSQD 0.04419417382415922f  // 1/sqrt(512)

// ---------------- scratch (device globals; no runtime allocation) ----------------
__device__ __align__(16) float g_pval[NB1];
__device__               int   g_pidx[NB1];
__device__               int   g_idx;
__device__ __align__(16) float g_Qvec[Dd];
__device__ __align__(16) float g_q[Dd];
__device__ __align__(16) float g_u[8 * Dd];
__device__ __align__(16) float g_c[8];
__device__ __align__(16) float g_scls[8];
__device__ __align__(16) float g_pm[NB3 * 8];
__device__ __align__(16) float g_pl[NB3 * 8];
__device__ __align__(16) float g_pacc[NB3 * 8 * Dd];
__device__ __align__(16) float g_M8[8];
__device__ __align__(16) float g_L8[8];
__device__ __align__(16) float g_s4[64 * Dd];
__device__ __align__(16) float g_O[Dd];
__device__ __align__(16) float g_O2[Dd];

// ---------------- K1: a1 = sigmoid(inputs @ w_enc + b_enc), argmax partials ------
__global__ void k1_kernel(const float* __restrict__ inp, const float* __restrict__ wenc,
                          const float* __restrict__ benc, float* __restrict__ A1)
{
    int warp = threadIdx.x >> 5, lane = threadIdx.x & 31;
    int row  = blockIdx.x * 8 + warp;   // 7500*8 = 60000 exactly
    const float4* ip = reinterpret_cast<const float4*>(inp + (size_t)row * Dd);
    const float4* wp = reinterpret_cast<const float4*>(wenc);
    float acc = 0.f;
#pragma unroll
    for (int it = 0; it < 4; it++) {
        int i = lane + it * 32;
        float4 a = __ldg(ip + i);
        float4 w = __ldg(wp + i);
        acc += a.x * w.x + a.y * w.y + a.z * w.z + a.w * w.w;
    }
#pragma unroll
    for (int o = 16; o; o >>= 1) acc += __shfl_xor_sync(0xffffffffu, acc, o);
    __shared__ float sv[8];
    __shared__ int   si[8];
    if (lane == 0) {
        float y = acc + benc[0];
        A1[row] = 1.f / (1.f + __expf(-y));   // sigmoid; monotone so argmax(y)=argmax(a1)
        sv[warp] = y; si[warp] = row;
    }
    __syncthreads();
    if (threadIdx.x == 0) {
        float bv = sv[0]; int bi = si[0];
        for (int w = 1; w < 8; w++) { if (sv[w] > bv) { bv = sv[w]; bi = si[w]; } }
        g_pval[blockIdx.x] = bv; g_pidx[blockIdx.x] = bi;
    }
}

// ---------------- K2a: argmax reduce + Q vector (1 block) ------------------------
__global__ void k2a_kernel(const float* __restrict__ inp)
{
    __shared__ float bv[512]; __shared__ int bi[512];
    int t = threadIdx.x;
    float best = -1e30f; int besti = 0x7fffffff;
    for (int b = t; b < NB1; b += 512) {
        float v = g_pval[b]; int ii = g_pidx[b];
        if (v > best || (v == best && ii < besti)) { best = v; besti = ii; }
    }
    bv[t] = best; bi[t] = besti;
    __syncthreads();
    for (int s = 256; s > 0; s >>= 1) {
        if (t < s) {
            if (bv[t + s] > bv[t] || (bv[t + s] == bv[t] && bi[t + s] < bi[t])) {
                bv[t] = bv[t + s]; bi[t] = bi[t + s];
            }
        }
        __syncthreads();
    }
    int idx = bi[0];
    if (t == 0) g_idx = idx;
    g_Qvec[t] = inp[(size_t)idx * Dd + t];
}

// ---------------- K2b: q = Q @ w_q + b_q (16 blocks x 256, split-K) --------------
__global__ void k2b_kernel(const float* __restrict__ wq, const float* __restrict__ bq)
{
    __shared__ float sQ[512];
    __shared__ float sred[256];
    int tid = threadIdx.x;
    int jl = tid & 31, ks = tid >> 5;
    int j = blockIdx.x * 32 + jl;
    sQ[tid] = g_Qvec[tid]; sQ[tid + 256] = g_Qvec[tid + 256];
    __syncthreads();
    float a = 0.f;
    int d0 = ks * 64;
#pragma unroll 8
    for (int d = d0; d < d0 + 64; d++) a += sQ[d] * __ldg(&wq[d * Dd + j]);
    sred[tid] = a;
    __syncthreads();
    if (ks == 0) {
        float s = a;
#pragma unroll
        for (int k = 1; k < 8; k++) s += sred[k * 32 + jl];
        g_q[j] = s + bq[j];
    }
}

// ---------------- K2c: u[h][t] = (w_k row t . q)_head / sqrt(D) ------------------
// 64 blocks x 256 (8 warps). Warp owns one wk row; coalesced float4 loads.
__global__ void k2c_kernel(const float* __restrict__ wk)
{
    __shared__ float sq[512];
    int tid = threadIdx.x;
    int warp = tid >> 5, lane = tid & 31;
    sq[tid] = g_q[tid]; sq[tid + 256] = g_q[tid + 256];
    __syncthreads();
    int t = blockIdx.x * 8 + warp;
    const float4* wrow = reinterpret_cast<const float4*>(wk + (size_t)t * Dd);
    const float4* q4   = reinterpret_cast<const float4*>(sq);
    float vp[4];
#pragma unroll
    for (int p = 0; p < 4; p++) {
        float4 w = __ldg(wrow + p * 32 + lane);
        float4 q = q4[p * 32 + lane];
        float v = w.x * q.x + w.y * q.y + w.z * q.z + w.w * q.w;
        // reduce within 16-lane half (lanes 0-15: head 2p, 16-31: head 2p+1)
        v += __shfl_xor_sync(0xffffffffu, v, 8);
        v += __shfl_xor_sync(0xffffffffu, v, 4);
        v += __shfl_xor_sync(0xffffffffu, v, 2);
        v += __shfl_xor_sync(0xffffffffu, v, 1);
        vp[p] = v;
    }
#pragma unroll
    for (int p = 0; p < 4; p++) {
        if (lane == 0)  g_u[(2 * p) * Dd + t]     = vp[p] * RSQD;
        if (lane == 16) g_u[(2 * p + 1) * Dd + t] = vp[p] * RSQD;
    }
}

// ---------------- K2d: c[h] and cls raw score (1 block) --------------------------
__global__ void k2d_kernel(const float* __restrict__ bk, const float* __restrict__ cls)
{
    __shared__ float red[512]; __shared__ float c8[8];
    int t = threadIdx.x;
    red[t] = bk[t] * g_q[t];
    __syncthreads();
    if (t < 8) {
        float s = 0.f;
        for (int j = 0; j < 64; j++) s += red[t * 64 + j];
        s *= RSQD; c8[t] = s; g_c[t] = s;
    }
    __syncthreads();
    for (int h = 0; h < 8; h++) {
        red[t] = cls[t] * g_u[h * Dd + t];
        __syncthreads();
        for (int s = 256; s > 0; s >>= 1) { if (t < s) red[t] += red[t + s]; __syncthreads(); }
        if (t == 0) g_scls[h] = red[0] + c8[h];
        __syncthreads();
    }
}

// ---------------- K3: fused relu-shift + conv stencil + flash softmax ------------
__device__ __forceinline__ float2 loadxs(const float* __restrict__ inp,
                                         int gy, int gx, int d0, float2 qv)
{
    if ((unsigned)gy >= (unsigned)Hh || (unsigned)gx >= (unsigned)Hh)
        return make_float2(0.f, 0.f);
    int pp = gy * Hh + gx;
    if (pp >= Nn) pp -= Nn;   // padded tokens wrap to tokens 0..24
    float2 v = __ldg(reinterpret_cast<const float2*>(inp + (size_t)pp * Dd + d0));
    return make_float2(fmaxf(v.x - qv.x, 0.f), fmaxf(v.y - qv.y, 0.f));
}

__global__ void __launch_bounds__(256)
k3_kernel(const float* __restrict__ inp, float* __restrict__ ish,
          const float* __restrict__ convw, const float* __restrict__ convb)
{
    int b    = blockIdx.x;
    int i    = b >> 1;
    int half = b & 1;
    int j0   = half ? 123 : 0;
    int j1   = half ? 245 : 123;
    int c    = threadIdx.x;          // channel pair 0..255
    int d0   = c * 2;
    int warp = c >> 5, lane = c & 31;

    __shared__ float sxx[CCH * Dd];        // 32 KB conv-output stash
    __shared__ float sp[CCH][8][8];        // [token][warp][head] partial dots
    __shared__ float sS[CCH][8];           // final scores per chunk
    __shared__ __align__(16) float swf[CCH][8];   // softmax weights
    __shared__ float sR[8];                // rescale factor per head
    __shared__ float shm[8], shl[8], shc[8];

    float2 qv = *reinterpret_cast<const float2*>(g_Qvec + d0);
    float2 uu[8];
#pragma unroll
    for (int h = 0; h < 8; h++) uu[h] = *reinterpret_cast<const float2*>(g_u + h * Dd + d0);
    float w0[9], w1[9];
#pragma unroll
    for (int k = 0; k < 9; k++) {
        w0[k] = convw[(d0 + 0) * 9 + k];
        w1[k] = convw[(d0 + 1) * 9 + k];
    }
    float2 cb2 = *reinterpret_cast<const float2*>(convb + d0);
    float2 acc[8];
#pragma unroll
    for (int h = 0; h < 8; h++) acc[h] = make_float2(0.f, 0.f);

    if (c < 8) { shm[c] = -1e30f; shl[c] = 0.f; shc[c] = g_c[c]; }
    __syncthreads();

    // rolling 3x3 stencil window
    float2 wA0, wA1, wA2, wB0, wB1, wB2, wC0, wC1, wC2;
    wA0 = loadxs(inp, i - 1, j0 - 1, d0, qv); wA1 = loadxs(inp, i - 1, j0, d0, qv);
    wB0 = loadxs(inp, i,     j0 - 1, d0, qv); wB1 = loadxs(inp, i,     j0, d0, qv);
    wC0 = loadxs(inp, i + 1, j0 - 1, d0, qv); wC1 = loadxs(inp, i + 1, j0, d0, qv);

    for (int jb = j0; jb < j1; jb += CCH) {
        int cn = min(CCH, j1 - jb);
        // ---- phase A: conv + scores, no block syncs ----
        for (int t = 0; t < cn; t++) {
            int j = jb + t;
            wA2 = loadxs(inp, i - 1, j + 1, d0, qv);
            wB2 = loadxs(inp, i,     j + 1, d0, qv);
            wC2 = loadxs(inp, i + 1, j + 1, d0, qv);

            float2 xx = cb2;
            xx.x += w0[0] * wA0.x + w0[1] * wA1.x + w0[2] * wA2.x
                  + w0[3] * wB0.x + w0[4] * wB1.x + w0[5] * wB2.x
                  + w0[6] * wC0.x + w0[7] * wC1.x + w0[8] * wC2.x;
            xx.y += w1[0] * wA0.y + w1[1] * wA1.y + w1[2] * wA2.y
                  + w1[3] * wB0.y + w1[4] * wB1.y + w1[5] * wB2.y
                  + w1[6] * wC0.y + w1[7] * wC1.y + w1[8] * wC2.y;
            xx.x += wB1.x; xx.y += wB1.y;        // residual: conv + cnn

            int pp = i * Hh + j;
            if (pp < Nn)                          // i_shift output (owned center)
                *reinterpret_cast<float2*>(ish + (size_t)pp * Dd + d0) = wB1;

            *reinterpret_cast<float2*>(&sxx[t * Dd + d0]) = xx;

            float p[8];
#pragma unroll
            for (int h = 0; h < 8; h++) p[h] = xx.x * uu[h].x + xx.y * uu[h].y;
            // hierarchical 8-head reduce: 9 shfls total
#pragma unroll
            for (int h = 0; h < 4; h++) {          // xor 16: heads 0-3 -> lo, 4-7 -> hi
                float send = (lane & 16) ? p[h] : p[h + 4];
                float recv = __shfl_xor_sync(0xffffffffu, send, 16);
                p[h] = ((lane & 16) ? p[h + 4] : p[h]) + recv;
            }
#pragma unroll
            for (int h = 0; h < 2; h++) {          // xor 8
                float send = (lane & 8) ? p[h] : p[h + 2];
                float recv = __shfl_xor_sync(0xffffffffu, send, 8);
                p[h] = ((lane & 8) ? p[h + 2] : p[h]) + recv;
            }
            {                                       // xor 4
                float send = (lane & 4) ? p[0] : p[1];
                float recv = __shfl_xor_sync(0xffffffffu, send, 4);
                p[0] = ((lane & 4) ? p[1] : p[0]) + recv;
            }
            p[0] += __shfl_xor_sync(0xffffffffu, p[0], 2);
            p[0] += __shfl_xor_sync(0xffffffffu, p[0], 1);
            if ((lane & 3) == 0) sp[t][warp][lane >> 2] = p[0];   // head = lane>>2

            wA0 = wA1; wA1 = wA2;
            wB0 = wB1; wB1 = wB2;
            wC0 = wC1; wC1 = wC2;
        }
        __syncthreads();
        // ---- phase B1: parallel sum of warp partials (128 threads) ----
        if (c < cn * 8) {
            int t = c >> 3, h = c & 7;
            float s = shc[h];
#pragma unroll
            for (int w = 0; w < 8; w++) s += sp[t][w][h];
            sS[t][h] = s;
        }
        __syncthreads();
        // ---- phase B2: chunk softmax finalize (8 threads) ----
        if (c < 8) {
            float mold = shm[c], mx = mold;
            for (int t = 0; t < cn; t++) mx = fmaxf(mx, sS[t][c]);
            float R = __expf(mold - mx);
            float ls = shl[c] * R;
            for (int t = 0; t < cn; t++) {
                float w = __expf(sS[t][c] - mx);
                swf[t][c] = w; ls += w;
            }
            sR[c] = R; shm[c] = mx; shl[c] = ls;
        }
        __syncthreads();
        // ---- phase C: weighted accumulate ----
#pragma unroll
        for (int h = 0; h < 8; h++) { float R = sR[h]; acc[h].x *= R; acc[h].y *= R; }
        for (int t = 0; t < cn; t++) {
            float2 xx = *reinterpret_cast<float2*>(&sxx[t * Dd + d0]);
            float4 wa = *reinterpret_cast<float4*>(&swf[t][0]);
            float4 wb = *reinterpret_cast<float4*>(&swf[t][4]);
            acc[0].x += wa.x * xx.x; acc[0].y += wa.x * xx.y;
            acc[1].x += wa.y * xx.x; acc[1].y += wa.y * xx.y;
            acc[2].x += wa.z * xx.x; acc[2].y += wa.z * xx.y;
            acc[3].x += wa.w * xx.x; acc[3].y += wa.w * xx.y;
            acc[4].x += wb.x * xx.x; acc[4].y += wb.x * xx.y;
            acc[5].x += wb.y * xx.x; acc[5].y += wb.y * xx.y;
            acc[6].x += wb.z * xx.x; acc[6].y += wb.z * xx.y;
            acc[7].x += wb.w * xx.x; acc[7].y += wb.w * xx.y;
        }
        __syncthreads();   // protect sxx/sp/swf before next chunk overwrites
    }

    if (c < 8) { g_pm[b * 8 + c] = shm[c]; g_pl[b * 8 + c] = shl[c]; }
#pragma unroll
    for (int h = 0; h < 8; h++)
        *reinterpret_cast<float2*>(&g_pacc[(size_t)(b * 8 + h) * Dd + d0]) = acc[h];
}

// ---------------- K4a: per-head global M, L --------------------------------------
__global__ void k4a_kernel()
{
    int h = blockIdx.x, t = threadIdx.x;
    __shared__ float red[512]; __shared__ float sM;
    float mv = (t < NB3) ? g_pm[t * 8 + h] : -1e30f;
    red[t] = mv;
    __syncthreads();
    for (int s = 256; s > 0; s >>= 1) { if (t < s) red[t] = fmaxf(red[t], red[t + s]); __syncthreads(); }
    if (t == 0) sM = fmaxf(red[0], g_scls[h]);
    __syncthreads();
    float M = sM;
    red[t] = (t < NB3) ? g_pl[t * 8 + h] * __expf(mv - M) : 0.f;
    __syncthreads();
    for (int s = 256; s > 0; s >>= 1) { if (t < s) red[t] += red[t + s]; __syncthreads(); }
    if (t == 0) { g_M8[h] = M; g_L8[h] = red[0] + __expf(g_scls[h] - M); }
}

// ---------------- K4b: weighted partial accumulate (64 blocks) -------------------
__global__ void k4b_kernel()
{
    int h = blockIdx.x >> 3, part = blockIdx.x & 7;
    int t = threadIdx.x;
    int b0 = part * 62, b1 = min(NB3, b0 + 62);
    int nb = b1 - b0;
    __shared__ float see[62];
    if (t < nb) see[t] = __expf(g_pm[(b0 + t) * 8 + h] - g_M8[h]);
    __syncthreads();
    float a = 0.f;
#pragma unroll 4
    for (int k = 0; k < nb; k++)
        a += see[k] * g_pacc[((size_t)(b0 + k) * 8 + h) * Dd + t];
    g_s4[(size_t)blockIdx.x * Dd + t] = a;   // layout [h*8+part][Dd]
}

// ---------------- K5a: O = q + s @ w_v + b_v (16 blocks x 256, split-K) ----------
// folds the k4c combine: s[d] = (sum parts + ecls*cls[d]) / L
__global__ void k5a_kernel(const float* __restrict__ cls,
                           const float* __restrict__ wv, const float* __restrict__ bv)
{
    __shared__ float ss[512];
    __shared__ float sred[256];
    int tid = threadIdx.x;
    int jl = tid & 31, ks = tid >> 5;
    int j = blockIdx.x * 32 + jl;
    int h = blockIdx.x >> 1;   // constant per block
    float ecls = __expf(g_scls[h] - g_M8[h]);
    float invL = 1.f / g_L8[h];
#pragma unroll
    for (int r = 0; r < 2; r++) {
        int d = tid + r * 256;
        float a = ecls * cls[d];
#pragma unroll
        for (int p = 0; p < 8; p++) a += g_s4[(size_t)(h * 8 + p) * Dd + d];
        ss[d] = a * invL;
    }
    __syncthreads();
    float a = 0.f;
    int d0 = ks * 64;
#pragma unroll 8
    for (int d = d0; d < d0 + 64; d++) a += ss[d] * __ldg(&wv[d * Dd + j]);
    sred[tid] = a;
    __syncthreads();
    if (ks == 0) {
        float s = a;
#pragma unroll
        for (int k = 1; k < 8; k++) s += sred[k * 32 + jl];
        g_O[j] = g_q[j] + s + bv[j];
    }
}

// ---------------- K5b: O2 = O + relu(O @ w_o + b_o) (16 blocks x 256) ------------
__global__ void k5b_kernel(const float* __restrict__ wo, const float* __restrict__ bo)
{
    __shared__ float sO[512];
    __shared__ float sred[256];
    int tid = threadIdx.x;
    int jl = tid & 31, ks = tid >> 5;
    int j = blockIdx.x * 32 + jl;
    sO[tid] = g_O[tid]; sO[tid + 256] = g_O[tid + 256];
    __syncthreads();
    float a = 0.f;
    int d0 = ks * 64;
#pragma unroll 8
    for (int d = d0; d < d0 + 64; d++) a += sO[d] * __ldg(&wo[d * Dd + j]);
    sred[tid] = a;
    __syncthreads();
    if (ks == 0) {
        float s = a;
#pragma unroll
        for (int k = 1; k < 8; k++) s += sred[k * 32 + jl];
        g_O2[j] = g_O[j] + fmaxf(s + bo[j], 0.f);
    }
}

// ---------------- K5c: out = O2 @ w_fc + b_fc (1 block) --------------------------
__global__ void k5c_kernel(const float* __restrict__ wfc, const float* __restrict__ bfc,
                           float* __restrict__ outv)
{
    __shared__ float r0[512], r1[512];
    int j = threadIdx.x;
    float v = g_O2[j];
    r0[j] = v * wfc[j * 2 + 0];
    r1[j] = v * wfc[j * 2 + 1];
    __syncthreads();
    for (int s = 256; s > 0; s >>= 1) {
        if (j < s) { r0[j] += r0[j + s]; r1[j] += r1[j + s]; }
        __syncthreads();
    }
    if (j == 0) { outv[0] = r0[0] + bfc[0]; outv[1] = r1[0] + bfc[1]; }
}

// ---------------- launch ----------------------------------------------------------
extern "C" void kernel_launch(void* const* d_in, const int* in_sizes, int n_in,
                              void* d_out, int out_size)
{
    (void)in_sizes; (void)n_in; (void)out_size;
    const float* inp   = (const float*)d_in[0];
    const float* wenc  = (const float*)d_in[1];
    const float* benc  = (const float*)d_in[2];
    const float* cls   = (const float*)d_in[3];
    const float* convw = (const float*)d_in[4];
    const float* convb = (const float*)d_in[5];
    const float* wq    = (const float*)d_in[6];
    const float* bq    = (const float*)d_in[7];
    const float* wk    = (const float*)d_in[8];
    const float* bk    = (const float*)d_in[9];
    const float* wv    = (const float*)d_in[10];
    const float* bvv   = (const float*)d_in[11];
    const float* wo    = (const float*)d_in[12];
    const float* bo    = (const float*)d_in[13];
    const float* wfc   = (const float*)d_in[14];
    const float* bfc   = (const float*)d_in[15];

    float* out    = (float*)d_out;
    float* ishift = out + 2;                          // i_shift: (1, 60000, 512)
    float* A1     = out + 2 + (size_t)Nn * Dd;        // A1: (1, 60000)

    k1_kernel <<<NB1, 256>>>(inp, wenc, benc, A1);
    k2a_kernel<<<1, 512>>>(inp);
    k2b_kernel<<<16, 256>>>(wq, bq);
    k2c_kernel<<<64, 256>>>(wk);
    k2d_kernel<<<1, 512>>>(bk, cls);
    k3_kernel <<<NB3, 256>>>(inp, ishift, convw, convb);
    k4a_kernel<<<8, 512>>>();
    k4b_kernel<<<64, 512>>>();
    k5a_kernel<<<16, 256>>>(cls, wv, bvv);
    k5b_kernel<<<16, 256>>>(wo, bo);
    k5c_kernel<<<1, 512>>>(wfc, bfc, out);
}